// round 1
// baseline (speedup 1.0000x reference)
#include <cuda_runtime.h>

#define NN 100000
#define NE 1600000
#define NG 256
#define HID 64

// ---- static scratch (no allocations allowed) ----
__device__ __align__(128) float g_xw[NN * HID];
__device__ __align__(128) float g_aggA[NN * HID];
__device__ __align__(128) float g_aggB[NN * HID];
__device__ float g_deg[NN];       // deg, then overwritten with dinv = rsqrt(deg)
__device__ float g_norm[NE];
__device__ float g_sums[NG];
__device__ float g_cnt[NG];

// -------------------- degree / norm precompute --------------------
__global__ void k_deg_init(int n) {
    int i = blockIdx.x * blockDim.x + threadIdx.x;
    if (i < n) g_deg[i] = 1.0f;             // self-loop weight
    if (i < NG) { g_sums[i] = 0.f; g_cnt[i] = 0.f; }
}

__global__ void k_deg_acc(const int* __restrict__ dst, const float* __restrict__ w, int E) {
    int e = blockIdx.x * blockDim.x + threadIdx.x;
    if (e < E) atomicAdd(&g_deg[dst[e]], w[e]);
}

__global__ void k_dinv(int n) {
    int i = blockIdx.x * blockDim.x + threadIdx.x;
    if (i < n) g_deg[i] = rsqrtf(g_deg[i]);
}

__global__ void k_norm(const int* __restrict__ src, const int* __restrict__ dst,
                       const float* __restrict__ w, int E) {
    int e = blockIdx.x * blockDim.x + threadIdx.x;
    if (e < E) g_norm[e] = g_deg[src[e]] * w[e] * g_deg[dst[e]];
}

// -------------------- GEMM: xw = act(X) @ W ; agg_init = xw/deg + b --------------------
// 64 rows per block, 256 threads: 4 threads/row, 16 output cols each.
__global__ __launch_bounds__(256) void k_gemm(
    const float* __restrict__ Xext, const float* __restrict__ W, const float* __restrict__ b,
    int sel_in, int sel_out, int relu_in, int n)
{
    __shared__ float Ws[64 * 64];
    __shared__ float Xs[64 * 65];   // +1 pad: conflict-free column reads

    const float* X = (sel_in == 0) ? Xext : (sel_in == 1 ? g_aggA : g_aggB);
    float* agg = (sel_out == 1) ? g_aggA : g_aggB;

    int tid = threadIdx.x;
    int row0 = blockIdx.x * 64;

    const float4* W4 = (const float4*)W;
    float4* Ws4 = (float4*)Ws;
    #pragma unroll
    for (int i = 0; i < 4; i++) Ws4[tid + 256 * i] = W4[tid + 256 * i];

    const float4* X4 = (const float4*)(X + (size_t)row0 * 64);
    #pragma unroll
    for (int i = 0; i < 4; i++) {
        int idx = tid + 256 * i;           // float4 index in 64x16 tile
        int r = idx >> 4, c4 = idx & 15;
        if (row0 + r < n) {
            float4 v = X4[idx];
            if (relu_in) {
                v.x = fmaxf(v.x, 0.f); v.y = fmaxf(v.y, 0.f);
                v.z = fmaxf(v.z, 0.f); v.w = fmaxf(v.w, 0.f);
            }
            float* p = &Xs[r * 65 + c4 * 4];
            p[0] = v.x; p[1] = v.y; p[2] = v.z; p[3] = v.w;
        }
    }
    __syncthreads();

    int r = tid >> 2;
    int cs = (tid & 3) * 16;
    int row = row0 + r;
    if (row >= n) return;

    float acc[16];
    #pragma unroll
    for (int c = 0; c < 16; c++) acc[c] = 0.f;

    #pragma unroll
    for (int k = 0; k < 64; k++) {
        float xv = Xs[r * 65 + k];
        const float4* wr = (const float4*)&Ws[k * 64 + cs];
        #pragma unroll
        for (int c4 = 0; c4 < 4; c4++) {
            float4 wv = wr[c4];
            acc[c4 * 4 + 0] += xv * wv.x;
            acc[c4 * 4 + 1] += xv * wv.y;
            acc[c4 * 4 + 2] += xv * wv.z;
            acc[c4 * 4 + 3] += xv * wv.w;
        }
    }

    float dv = g_deg[row];     // dinv
    float inv = dv * dv;       // 1/deg
    float4* xwp = (float4*)(g_xw + (size_t)row * 64 + cs);
    float4* agp = (float4*)(agg + (size_t)row * 64 + cs);
    const float4* b4 = (const float4*)(b + cs);
    #pragma unroll
    for (int c4 = 0; c4 < 4; c4++) {
        float4 a;
        a.x = acc[c4 * 4 + 0]; a.y = acc[c4 * 4 + 1];
        a.z = acc[c4 * 4 + 2]; a.w = acc[c4 * 4 + 3];
        xwp[c4] = a;
        float4 bb = b4[c4];
        float4 o;
        o.x = a.x * inv + bb.x; o.y = a.y * inv + bb.y;
        o.z = a.z * inv + bb.z; o.w = a.w * inv + bb.w;
        agp[c4] = o;
    }
}

// -------------------- edge scatter: agg[dst] += xw[src] * norm --------------------
// 8 threads per edge, each does 2x float4 gather + 2x red.add.v4.f32
__global__ __launch_bounds__(256) void k_scatter(
    const int* __restrict__ src, const int* __restrict__ dst, int sel_out, int E)
{
    int t = blockIdx.x * blockDim.x + threadIdx.x;
    int e = t >> 3;
    if (e >= E) return;
    int j = t & 7;
    float* agg = (sel_out == 1) ? g_aggA : g_aggB;

    int s = __ldg(src + e);
    int d = __ldg(dst + e);
    float nv = __ldg(g_norm + e);

    const float4* x4 = (const float4*)g_xw;
    float4 a = __ldg(&x4[(size_t)s * 16 + j * 2]);
    float4 bq = __ldg(&x4[(size_t)s * 16 + j * 2 + 1]);

    float* base = agg + (size_t)d * 64 + j * 8;
    asm volatile("red.global.add.v4.f32 [%0], {%1,%2,%3,%4};"
                 :: "l"(base), "f"(a.x * nv), "f"(a.y * nv), "f"(a.z * nv), "f"(a.w * nv)
                 : "memory");
    asm volatile("red.global.add.v4.f32 [%0], {%1,%2,%3,%4};"
                 :: "l"(base + 4), "f"(bq.x * nv), "f"(bq.y * nv), "f"(bq.z * nv), "f"(bq.w * nv)
                 : "memory");
}

// -------------------- readout + pooled mean (batch is sorted) --------------------
__global__ __launch_bounds__(256) void k_readout(
    const float* __restrict__ Wr0, const float* __restrict__ br0,
    const float* __restrict__ Wr1, const float* __restrict__ br1,
    const int* __restrict__ batch, int n)
{
    __shared__ float W0s[64 * 32];
    __shared__ float W1s[32];
    __shared__ float b0s[32];
    int tid = threadIdx.x;
    for (int i = tid; i < 2048; i += 256) W0s[i] = Wr0[i];
    if (tid < 32) { W1s[tid] = Wr1[tid]; b0s[tid] = br0[tid]; }
    __syncthreads();

    int i = blockIdx.x * 256 + tid;
    float s = 0.f, cv = 0.f;
    int g = -1;
    if (i < n) {
        g = batch[i];
        cv = 1.f;
        float acc[32];
        #pragma unroll
        for (int c = 0; c < 32; c++) acc[c] = b0s[c];
        const float4* row = (const float4*)(g_aggA + (size_t)i * 64);
        #pragma unroll
        for (int k4 = 0; k4 < 16; k4++) {
            float4 v = __ldg(row + k4);
            const float* w0 = &W0s[(k4 * 4) * 32];
            #pragma unroll
            for (int c = 0; c < 32; c++) acc[c] += v.x * w0[c];
            #pragma unroll
            for (int c = 0; c < 32; c++) acc[c] += v.y * w0[32 + c];
            #pragma unroll
            for (int c = 0; c < 32; c++) acc[c] += v.z * w0[64 + c];
            #pragma unroll
            for (int c = 0; c < 32; c++) acc[c] += v.w * w0[96 + c];
        }
        s = br1[0];
        #pragma unroll
        for (int c = 0; c < 32; c++) s += fmaxf(acc[c], 0.f) * W1s[c];
    }

    // warp-level segmented inclusive scan (batch sorted -> segments contiguous)
    const unsigned full = 0xffffffffu;
    int lane = tid & 31;
    #pragma unroll
    for (int off = 1; off < 32; off <<= 1) {
        float so = __shfl_up_sync(full, s, off);
        float co = __shfl_up_sync(full, cv, off);
        int go = __shfl_up_sync(full, g, off);
        if (lane >= off && go == g) { s += so; cv += co; }
    }
    int gn = __shfl_down_sync(full, g, 1);
    if ((lane == 31 || gn != g) && g >= 0) {
        atomicAdd(&g_sums[g], s);
        atomicAdd(&g_cnt[g], cv);
    }
}

__global__ void k_finalize(float* __restrict__ out) {
    int g = threadIdx.x;
    out[g] = g_sums[g] / fmaxf(g_cnt[g], 1.0f);
}

// -------------------- launch --------------------
extern "C" void kernel_launch(void* const* d_in, const int* in_sizes, int n_in,
                              void* d_out, int out_size)
{
    const float* x   = (const float*)d_in[0];
    const int*   ei  = (const int*)d_in[1];
    const float* ew  = (const float*)d_in[2];
    const int* batch = (const int*)d_in[3];
    const float* W0  = (const float*)d_in[4];
    const float* b0  = (const float*)d_in[5];
    const float* W1  = (const float*)d_in[6];
    const float* b1  = (const float*)d_in[7];
    const float* W2  = (const float*)d_in[8];
    const float* b2  = (const float*)d_in[9];
    const float* Wr0 = (const float*)d_in[10];
    const float* br0 = (const float*)d_in[11];
    const float* Wr1 = (const float*)d_in[12];
    const float* br1 = (const float*)d_in[13];
    float* out = (float*)d_out;

    int n = in_sizes[0] / HID;       // 100000
    int E = in_sizes[2];             // 1600000
    const int* src = ei;
    const int* dst = ei + E;

    k_deg_init<<<(n + 255) / 256, 256>>>(n);
    k_deg_acc<<<(E + 255) / 256, 256>>>(dst, ew, E);
    k_dinv<<<(n + 255) / 256, 256>>>(n);
    k_norm<<<(E + 255) / 256, 256>>>(src, dst, ew, E);

    int gb = (n + 63) / 64;
    int sb = (E * 8 + 255) / 256;

    // layer 0: x -> aggA
    k_gemm<<<gb, 256>>>(x, W0, b0, /*in*/0, /*out*/1, /*relu*/0, n);
    k_scatter<<<sb, 256>>>(src, dst, 1, E);
    // layer 1: relu(aggA) -> aggB
    k_gemm<<<gb, 256>>>(nullptr, W1, b1, 1, 2, 1, n);
    k_scatter<<<sb, 256>>>(src, dst, 2, E);
    // layer 2: relu(aggB) -> aggA (no output activation)
    k_gemm<<<gb, 256>>>(nullptr, W2, b2, 2, 1, 1, n);
    k_scatter<<<sb, 256>>>(src, dst, 1, E);

    k_readout<<<(n + 255) / 256, 256>>>(Wr0, br0, Wr1, br1, batch, n);
    k_finalize<<<1, 256>>>(out);
}

// round 2
// speedup vs baseline: 1.0005x; 1.0005x over previous
#include <cuda_runtime.h>

#define NN 100000
#define NE 1600000
#define NG 256
#define HID 64

// ---- static scratch (no allocations allowed) ----
__device__ __align__(128) float g_xw[NN * HID];
__device__ __align__(128) float g_aggA[NN * HID];
__device__ __align__(128) float g_aggB[NN * HID];
__device__ float g_deg[NN];       // deg, then overwritten with dinv = rsqrt(deg)
__device__ float g_norm[NE];
__device__ float g_sums[NG];
__device__ float g_cnt[NG];

// -------------------- degree / norm precompute --------------------
__global__ void k_deg_init(int n) {
    int i = blockIdx.x * blockDim.x + threadIdx.x;
    if (i < n) g_deg[i] = 1.0f;             // self-loop weight
    if (i < NG) { g_sums[i] = 0.f; g_cnt[i] = 0.f; }
}

__global__ void k_deg_acc(const int* __restrict__ dst, const float* __restrict__ w, int E) {
    int e = blockIdx.x * blockDim.x + threadIdx.x;
    if (e < E) atomicAdd(&g_deg[dst[e]], w[e]);
}

__global__ void k_dinv(int n) {
    int i = blockIdx.x * blockDim.x + threadIdx.x;
    if (i < n) g_deg[i] = rsqrtf(g_deg[i]);
}

__global__ void k_norm(const int* __restrict__ src, const int* __restrict__ dst,
                       const float* __restrict__ w, int E) {
    int e = blockIdx.x * blockDim.x + threadIdx.x;
    if (e < E) g_norm[e] = g_deg[src[e]] * w[e] * g_deg[dst[e]];
}

// -------------------- GEMM: xw = act(X) @ W ; agg_init = xw/deg + b --------------------
// 64 rows per block, 256 threads: 4 threads/row, 16 output cols each.
__global__ __launch_bounds__(256) void k_gemm(
    const float* __restrict__ Xext, const float* __restrict__ W, const float* __restrict__ b,
    int sel_in, int sel_out, int relu_in, int n)
{
    __shared__ float Ws[64 * 64];
    __shared__ float Xs[64 * 65];   // +1 pad: conflict-free column reads

    const float* X = (sel_in == 0) ? Xext : (sel_in == 1 ? g_aggA : g_aggB);
    float* agg = (sel_out == 1) ? g_aggA : g_aggB;

    int tid = threadIdx.x;
    int row0 = blockIdx.x * 64;

    const float4* W4 = (const float4*)W;
    float4* Ws4 = (float4*)Ws;
    #pragma unroll
    for (int i = 0; i < 4; i++) Ws4[tid + 256 * i] = W4[tid + 256 * i];

    const float4* X4 = (const float4*)(X + (size_t)row0 * 64);
    #pragma unroll
    for (int i = 0; i < 4; i++) {
        int idx = tid + 256 * i;           // float4 index in 64x16 tile
        int r = idx >> 4, c4 = idx & 15;
        if (row0 + r < n) {
            float4 v = X4[idx];
            if (relu_in) {
                v.x = fmaxf(v.x, 0.f); v.y = fmaxf(v.y, 0.f);
                v.z = fmaxf(v.z, 0.f); v.w = fmaxf(v.w, 0.f);
            }
            float* p = &Xs[r * 65 + c4 * 4];
            p[0] = v.x; p[1] = v.y; p[2] = v.z; p[3] = v.w;
        }
    }
    __syncthreads();

    int r = tid >> 2;
    int cs = (tid & 3) * 16;
    int row = row0 + r;
    if (row >= n) return;

    float acc[16];
    #pragma unroll
    for (int c = 0; c < 16; c++) acc[c] = 0.f;

    #pragma unroll
    for (int k = 0; k < 64; k++) {
        float xv = Xs[r * 65 + k];
        const float4* wr = (const float4*)&Ws[k * 64 + cs];
        #pragma unroll
        for (int c4 = 0; c4 < 4; c4++) {
            float4 wv = wr[c4];
            acc[c4 * 4 + 0] += xv * wv.x;
            acc[c4 * 4 + 1] += xv * wv.y;
            acc[c4 * 4 + 2] += xv * wv.z;
            acc[c4 * 4 + 3] += xv * wv.w;
        }
    }

    float dv = g_deg[row];     // dinv
    float inv = dv * dv;       // 1/deg
    float4* xwp = (float4*)(g_xw + (size_t)row * 64 + cs);
    float4* agp = (float4*)(agg + (size_t)row * 64 + cs);
    const float4* b4 = (const float4*)(b + cs);
    #pragma unroll
    for (int c4 = 0; c4 < 4; c4++) {
        float4 a;
        a.x = acc[c4 * 4 + 0]; a.y = acc[c4 * 4 + 1];
        a.z = acc[c4 * 4 + 2]; a.w = acc[c4 * 4 + 3];
        xwp[c4] = a;
        float4 bb = b4[c4];
        float4 o;
        o.x = a.x * inv + bb.x; o.y = a.y * inv + bb.y;
        o.z = a.z * inv + bb.z; o.w = a.w * inv + bb.w;
        agp[c4] = o;
    }
}

// -------------------- edge scatter: agg[dst] += xw[src] * norm --------------------
// 8 threads per edge, each does 2x float4 gather + 2x red.add.v4.f32
__global__ __launch_bounds__(256) void k_scatter(
    const int* __restrict__ src, const int* __restrict__ dst, int sel_out, int E)
{
    int t = blockIdx.x * blockDim.x + threadIdx.x;
    int e = t >> 3;
    if (e >= E) return;
    int j = t & 7;
    float* agg = (sel_out == 1) ? g_aggA : g_aggB;

    int s = __ldg(src + e);
    int d = __ldg(dst + e);
    float nv = __ldg(g_norm + e);

    const float4* x4 = (const float4*)g_xw;
    float4 a = __ldg(&x4[(size_t)s * 16 + j * 2]);
    float4 bq = __ldg(&x4[(size_t)s * 16 + j * 2 + 1]);

    float* base = agg + (size_t)d * 64 + j * 8;
    asm volatile("red.global.add.v4.f32 [%0], {%1,%2,%3,%4};"
                 :: "l"(base), "f"(a.x * nv), "f"(a.y * nv), "f"(a.z * nv), "f"(a.w * nv)
                 : "memory");
    asm volatile("red.global.add.v4.f32 [%0], {%1,%2,%3,%4};"
                 :: "l"(base + 4), "f"(bq.x * nv), "f"(bq.y * nv), "f"(bq.z * nv), "f"(bq.w * nv)
                 : "memory");
}

// -------------------- readout + pooled mean (batch is sorted) --------------------
__global__ __launch_bounds__(256) void k_readout(
    const float* __restrict__ Wr0, const float* __restrict__ br0,
    const float* __restrict__ Wr1, const float* __restrict__ br1,
    const int* __restrict__ batch, int n)
{
    __shared__ float W0s[64 * 32];
    __shared__ float W1s[32];
    __shared__ float b0s[32];
    int tid = threadIdx.x;
    for (int i = tid; i < 2048; i += 256) W0s[i] = Wr0[i];
    if (tid < 32) { W1s[tid] = Wr1[tid]; b0s[tid] = br0[tid]; }
    __syncthreads();

    int i = blockIdx.x * 256 + tid;
    float s = 0.f, cv = 0.f;
    int g = -1;
    if (i < n) {
        g = batch[i];
        cv = 1.f;
        float acc[32];
        #pragma unroll
        for (int c = 0; c < 32; c++) acc[c] = b0s[c];
        const float4* row = (const float4*)(g_aggA + (size_t)i * 64);
        #pragma unroll
        for (int k4 = 0; k4 < 16; k4++) {
            float4 v = __ldg(row + k4);
            const float* w0 = &W0s[(k4 * 4) * 32];
            #pragma unroll
            for (int c = 0; c < 32; c++) acc[c] += v.x * w0[c];
            #pragma unroll
            for (int c = 0; c < 32; c++) acc[c] += v.y * w0[32 + c];
            #pragma unroll
            for (int c = 0; c < 32; c++) acc[c] += v.z * w0[64 + c];
            #pragma unroll
            for (int c = 0; c < 32; c++) acc[c] += v.w * w0[96 + c];
        }
        s = br1[0];
        #pragma unroll
        for (int c = 0; c < 32; c++) s += fmaxf(acc[c], 0.f) * W1s[c];
    }

    // warp-level segmented inclusive scan (batch sorted -> segments contiguous)
    const unsigned full = 0xffffffffu;
    int lane = tid & 31;
    #pragma unroll
    for (int off = 1; off < 32; off <<= 1) {
        float so = __shfl_up_sync(full, s, off);
        float co = __shfl_up_sync(full, cv, off);
        int go = __shfl_up_sync(full, g, off);
        if (lane >= off && go == g) { s += so; cv += co; }
    }
    int gn = __shfl_down_sync(full, g, 1);
    if ((lane == 31 || gn != g) && g >= 0) {
        atomicAdd(&g_sums[g], s);
        atomicAdd(&g_cnt[g], cv);
    }
}

__global__ void k_finalize(float* __restrict__ out) {
    int g = threadIdx.x;
    out[g] = g_sums[g] / fmaxf(g_cnt[g], 1.0f);
}

// -------------------- launch --------------------
extern "C" void kernel_launch(void* const* d_in, const int* in_sizes, int n_in,
                              void* d_out, int out_size)
{
    const float* x   = (const float*)d_in[0];
    const int*   ei  = (const int*)d_in[1];
    const float* ew  = (const float*)d_in[2];
    const int* batch = (const int*)d_in[3];
    const float* W0  = (const float*)d_in[4];
    const float* b0  = (const float*)d_in[5];
    const float* W1  = (const float*)d_in[6];
    const float* b1  = (const float*)d_in[7];
    const float* W2  = (const float*)d_in[8];
    const float* b2  = (const float*)d_in[9];
    const float* Wr0 = (const float*)d_in[10];
    const float* br0 = (const float*)d_in[11];
    const float* Wr1 = (const float*)d_in[12];
    const float* br1 = (const float*)d_in[13];
    float* out = (float*)d_out;

    int n = in_sizes[0] / HID;       // 100000
    int E = in_sizes[2];             // 1600000
    const int* src = ei;
    const int* dst = ei + E;

    k_deg_init<<<(n + 255) / 256, 256>>>(n);
    k_deg_acc<<<(E + 255) / 256, 256>>>(dst, ew, E);
    k_dinv<<<(n + 255) / 256, 256>>>(n);
    k_norm<<<(E + 255) / 256, 256>>>(src, dst, ew, E);

    int gb = (n + 63) / 64;
    int sb = (E * 8 + 255) / 256;

    // layer 0: x -> aggA
    k_gemm<<<gb, 256>>>(x, W0, b0, /*in*/0, /*out*/1, /*relu*/0, n);
    k_scatter<<<sb, 256>>>(src, dst, 1, E);
    // layer 1: relu(aggA) -> aggB
    k_gemm<<<gb, 256>>>(nullptr, W1, b1, 1, 2, 1, n);
    k_scatter<<<sb, 256>>>(src, dst, 2, E);
    // layer 2: relu(aggB) -> aggA (no output activation)
    k_gemm<<<gb, 256>>>(nullptr, W2, b2, 2, 1, 1, n);
    k_scatter<<<sb, 256>>>(src, dst, 1, E);

    k_readout<<<(n + 255) / 256, 256>>>(Wr0, br0, Wr1, br1, batch, n);
    k_finalize<<<1, 256>>>(out);
}

// round 3
// speedup vs baseline: 1.4291x; 1.4284x over previous
#include <cuda_runtime.h>

#define NN 100000
#define NE 1600000
#define NG 256
#define HID 64

// ---- static scratch (no allocations allowed) ----
__device__ __align__(128) float g_xw[NN * HID];
__device__ __align__(128) float g_aggA[NN * HID];
__device__ __align__(128) float g_aggB[NN * HID];
__device__ float g_deg[NN];        // deg, then overwritten with dinv = rsqrt(deg)
__device__ int   g_hist[NN];       // in-degree histogram
__device__ int   g_row[NN + 1];    // CSR row offsets (by dst)
__device__ int   g_cursor[NN];     // counting-sort cursors
__device__ int   g_bsum[128];      // scan block sums
__device__ int   g_srcs[NE];       // CSR: src node per sorted edge
__device__ float g_norms[NE];      // CSR: norm per sorted edge
__device__ float g_sums[NG];
__device__ float g_cnt[NG];

// -------------------- init --------------------
__global__ void k_init(int n) {
    int i = blockIdx.x * blockDim.x + threadIdx.x;
    if (i < n) { g_deg[i] = 1.0f; g_hist[i] = 0; }
    if (i < NG) { g_sums[i] = 0.f; g_cnt[i] = 0.f; }
}

// -------------------- degree + histogram (one pass over edges) --------------------
__global__ void k_deg_hist(const int* __restrict__ dst, const float* __restrict__ w, int E) {
    int e = blockIdx.x * blockDim.x + threadIdx.x;
    if (e < E) {
        int d = dst[e];
        atomicAdd(&g_deg[d], w[e]);
        atomicAdd(&g_hist[d], 1);
    }
}

__global__ void k_dinv(int n) {
    int i = blockIdx.x * blockDim.x + threadIdx.x;
    if (i < n) g_deg[i] = rsqrtf(g_deg[i]);
}

// -------------------- 2-level exclusive scan of g_hist -> g_row --------------------
__global__ __launch_bounds__(1024) void k_scanA(int n) {
    __shared__ int ws[32];
    int t = threadIdx.x;
    int i = blockIdx.x * 1024 + t;
    int v = (i < n) ? g_hist[i] : 0;
    const unsigned full = 0xffffffffu;
    int lane = t & 31, warp = t >> 5;
    int x = v;
    #pragma unroll
    for (int off = 1; off < 32; off <<= 1) {
        int y = __shfl_up_sync(full, x, off);
        if (lane >= off) x += y;
    }
    if (lane == 31) ws[warp] = x;
    __syncthreads();
    if (warp == 0) {
        int y = ws[lane];
        #pragma unroll
        for (int off = 1; off < 32; off <<= 1) {
            int z = __shfl_up_sync(full, y, off);
            if (lane >= off) y += z;
        }
        ws[lane] = y;
    }
    __syncthreads();
    int blockpref = (warp > 0) ? ws[warp - 1] : 0;
    int incl = x + blockpref;
    if (i < n) g_row[i] = incl - v;            // exclusive within block
    if (t == 1023) g_bsum[blockIdx.x] = incl;  // block total
}

__global__ void k_scanB(int nb) {
    if (threadIdx.x == 0) {
        int acc = 0;
        for (int b = 0; b < nb; b++) { int v = g_bsum[b]; g_bsum[b] = acc; acc += v; }
    }
}

__global__ __launch_bounds__(1024) void k_scanC(int n, int E) {
    int i = blockIdx.x * 1024 + threadIdx.x;
    if (i < n) {
        int r = g_row[i] + g_bsum[blockIdx.x];
        g_row[i] = r;
        g_cursor[i] = r;
    }
    if (i == 0) g_row[n] = E;
}

// -------------------- counting-sort fill: CSR srcs/norms by dst --------------------
__global__ void k_fill(const int* __restrict__ src, const int* __restrict__ dst,
                       const float* __restrict__ w, int E) {
    int e = blockIdx.x * blockDim.x + threadIdx.x;
    if (e < E) {
        int s = src[e], d = dst[e];
        float nv = g_deg[s] * w[e] * g_deg[d];   // g_deg holds dinv here
        int pos = atomicAdd(&g_cursor[d], 1);
        g_srcs[pos] = s;
        g_norms[pos] = nv;
    }
}

// -------------------- GEMM: xw = act(X) @ W --------------------
// 64 rows per block, 256 threads: 4 threads/row, 16 output cols each.
__global__ __launch_bounds__(256) void k_gemm(
    const float* __restrict__ Xext, const float* __restrict__ W,
    int sel_in, int relu_in, int n)
{
    __shared__ float Ws[64 * 64];
    __shared__ float Xs[64 * 65];

    const float* X = (sel_in == 0) ? Xext : (sel_in == 1 ? g_aggA : g_aggB);

    int tid = threadIdx.x;
    int row0 = blockIdx.x * 64;

    const float4* W4 = (const float4*)W;
    float4* Ws4 = (float4*)Ws;
    #pragma unroll
    for (int i = 0; i < 4; i++) Ws4[tid + 256 * i] = W4[tid + 256 * i];

    const float4* X4 = (const float4*)(X + (size_t)row0 * 64);
    #pragma unroll
    for (int i = 0; i < 4; i++) {
        int idx = tid + 256 * i;
        int r = idx >> 4, c4 = idx & 15;
        if (row0 + r < n) {
            float4 v = X4[idx];
            if (relu_in) {
                v.x = fmaxf(v.x, 0.f); v.y = fmaxf(v.y, 0.f);
                v.z = fmaxf(v.z, 0.f); v.w = fmaxf(v.w, 0.f);
            }
            float* p = &Xs[r * 65 + c4 * 4];
            p[0] = v.x; p[1] = v.y; p[2] = v.z; p[3] = v.w;
        }
    }
    __syncthreads();

    int r = tid >> 2;
    int cs = (tid & 3) * 16;
    int row = row0 + r;
    if (row >= n) return;

    float acc[16];
    #pragma unroll
    for (int c = 0; c < 16; c++) acc[c] = 0.f;

    #pragma unroll
    for (int k = 0; k < 64; k++) {
        float xv = Xs[r * 65 + k];
        const float4* wr = (const float4*)&Ws[k * 64 + cs];
        #pragma unroll
        for (int c4 = 0; c4 < 4; c4++) {
            float4 wv = wr[c4];
            acc[c4 * 4 + 0] += xv * wv.x;
            acc[c4 * 4 + 1] += xv * wv.y;
            acc[c4 * 4 + 2] += xv * wv.z;
            acc[c4 * 4 + 3] += xv * wv.w;
        }
    }

    float4* xwp = (float4*)(g_xw + (size_t)row * 64 + cs);
    #pragma unroll
    for (int c4 = 0; c4 < 4; c4++) {
        float4 a;
        a.x = acc[c4 * 4 + 0]; a.y = acc[c4 * 4 + 1];
        a.z = acc[c4 * 4 + 2]; a.w = acc[c4 * 4 + 3];
        xwp[c4] = a;
    }
}

// -------------------- CSR gather: agg[n] = xw[n]/deg + b + sum_e xw[src_e]*norm_e --------------------
// 16 threads per node, each owns one float4 column slice. No atomics.
__global__ __launch_bounds__(256) void k_gather(
    const float* __restrict__ bias, int sel_out, int n)
{
    int t = blockIdx.x * blockDim.x + threadIdx.x;
    int node = t >> 4;
    if (node >= n) return;
    int j = t & 15;
    float* agg = (sel_out == 1) ? g_aggA : g_aggB;

    int start = __ldg(g_row + node);
    int end   = __ldg(g_row + node + 1);
    float dv = __ldg(g_deg + node);     // dinv
    float inv = dv * dv;                // 1/deg

    const float4* x4 = (const float4*)g_xw;
    float4 bb = __ldg(((const float4*)bias) + j);
    float4 self = __ldg(&x4[(size_t)node * 16 + j]);
    float ax = self.x * inv + bb.x;
    float ay = self.y * inv + bb.y;
    float az = self.z * inv + bb.z;
    float aw = self.w * inv + bb.w;

    int e = start;
    // unroll-by-2 for memory-level parallelism
    for (; e + 1 < end; e += 2) {
        int s0 = __ldg(g_srcs + e);
        int s1 = __ldg(g_srcs + e + 1);
        float n0 = __ldg(g_norms + e);
        float n1 = __ldg(g_norms + e + 1);
        float4 v0 = __ldg(&x4[(size_t)s0 * 16 + j]);
        float4 v1 = __ldg(&x4[(size_t)s1 * 16 + j]);
        ax += v0.x * n0; ay += v0.y * n0; az += v0.z * n0; aw += v0.w * n0;
        ax += v1.x * n1; ay += v1.y * n1; az += v1.z * n1; aw += v1.w * n1;
    }
    if (e < end) {
        int s0 = __ldg(g_srcs + e);
        float n0 = __ldg(g_norms + e);
        float4 v0 = __ldg(&x4[(size_t)s0 * 16 + j]);
        ax += v0.x * n0; ay += v0.y * n0; az += v0.z * n0; aw += v0.w * n0;
    }

    float4 o; o.x = ax; o.y = ay; o.z = az; o.w = aw;
    ((float4*)(agg + (size_t)node * 64))[j] = o;
}

// -------------------- readout + pooled mean (batch is sorted) --------------------
__global__ __launch_bounds__(256) void k_readout(
    const float* __restrict__ Wr0, const float* __restrict__ br0,
    const float* __restrict__ Wr1, const float* __restrict__ br1,
    const int* __restrict__ batch, int n)
{
    __shared__ float W0s[64 * 32];
    __shared__ float W1s[32];
    __shared__ float b0s[32];
    int tid = threadIdx.x;
    for (int i = tid; i < 2048; i += 256) W0s[i] = Wr0[i];
    if (tid < 32) { W1s[tid] = Wr1[tid]; b0s[tid] = br0[tid]; }
    __syncthreads();

    int i = blockIdx.x * 256 + tid;
    float s = 0.f, cv = 0.f;
    int g = -1;
    if (i < n) {
        g = batch[i];
        cv = 1.f;
        float acc[32];
        #pragma unroll
        for (int c = 0; c < 32; c++) acc[c] = b0s[c];
        const float4* row = (const float4*)(g_aggA + (size_t)i * 64);
        #pragma unroll
        for (int k4 = 0; k4 < 16; k4++) {
            float4 v = __ldg(row + k4);
            const float* w0 = &W0s[(k4 * 4) * 32];
            #pragma unroll
            for (int c = 0; c < 32; c++) acc[c] += v.x * w0[c];
            #pragma unroll
            for (int c = 0; c < 32; c++) acc[c] += v.y * w0[32 + c];
            #pragma unroll
            for (int c = 0; c < 32; c++) acc[c] += v.z * w0[64 + c];
            #pragma unroll
            for (int c = 0; c < 32; c++) acc[c] += v.w * w0[96 + c];
        }
        s = br1[0];
        #pragma unroll
        for (int c = 0; c < 32; c++) s += fmaxf(acc[c], 0.f) * W1s[c];
    }

    const unsigned full = 0xffffffffu;
    int lane = tid & 31;
    #pragma unroll
    for (int off = 1; off < 32; off <<= 1) {
        float so = __shfl_up_sync(full, s, off);
        float co = __shfl_up_sync(full, cv, off);
        int go = __shfl_up_sync(full, g, off);
        if (lane >= off && go == g) { s += so; cv += co; }
    }
    int gn = __shfl_down_sync(full, g, 1);
    if ((lane == 31 || gn != g) && g >= 0) {
        atomicAdd(&g_sums[g], s);
        atomicAdd(&g_cnt[g], cv);
    }
}

__global__ void k_finalize(float* __restrict__ out) {
    int g = threadIdx.x;
    out[g] = g_sums[g] / fmaxf(g_cnt[g], 1.0f);
}

// -------------------- launch --------------------
extern "C" void kernel_launch(void* const* d_in, const int* in_sizes, int n_in,
                              void* d_out, int out_size)
{
    const float* x   = (const float*)d_in[0];
    const int*   ei  = (const int*)d_in[1];
    const float* ew  = (const float*)d_in[2];
    const int* batch = (const int*)d_in[3];
    const float* W0  = (const float*)d_in[4];
    const float* b0  = (const float*)d_in[5];
    const float* W1  = (const float*)d_in[6];
    const float* b1  = (const float*)d_in[7];
    const float* W2  = (const float*)d_in[8];
    const float* b2  = (const float*)d_in[9];
    const float* Wr0 = (const float*)d_in[10];
    const float* br0 = (const float*)d_in[11];
    const float* Wr1 = (const float*)d_in[12];
    const float* br1 = (const float*)d_in[13];
    float* out = (float*)d_out;

    int n = in_sizes[0] / HID;       // 100000
    int E = in_sizes[2];             // 1600000
    const int* src = ei;
    const int* dst = ei + E;

    int nb = (n + 1023) / 1024;

    // ---- CSR build (once per launch) ----
    k_init<<<(n + 255) / 256, 256>>>(n);
    k_deg_hist<<<(E + 255) / 256, 256>>>(dst, ew, E);
    k_dinv<<<(n + 255) / 256, 256>>>(n);
    k_scanA<<<nb, 1024>>>(n);
    k_scanB<<<1, 32>>>(nb);
    k_scanC<<<nb, 1024>>>(n, E);
    k_fill<<<(E + 255) / 256, 256>>>(src, dst, ew, E);

    int gb = (n + 63) / 64;
    int ga = (n * 16 + 255) / 256;

    // layer 0: x -> aggA
    k_gemm<<<gb, 256>>>(x, W0, /*in*/0, /*relu*/0, n);
    k_gather<<<ga, 256>>>(b0, /*out*/1, n);
    // layer 1: relu(aggA) -> aggB
    k_gemm<<<gb, 256>>>(nullptr, W1, 1, 1, n);
    k_gather<<<ga, 256>>>(b1, 2, n);
    // layer 2: relu(aggB) -> aggA (no output activation)
    k_gemm<<<gb, 256>>>(nullptr, W2, 2, 1, n);
    k_gather<<<ga, 256>>>(b2, 1, n);

    k_readout<<<(n + 255) / 256, 256>>>(Wr0, br0, Wr1, br1, batch, n);
    k_finalize<<<1, 256>>>(out);
}

// round 4
// speedup vs baseline: 1.5183x; 1.0624x over previous
#include <cuda_runtime.h>
#include <cuda_fp16.h>

#define NN 100000
#define NE 1600000
#define NG 256
#define HID 64

// ---- static scratch (no allocations allowed) ----
__device__ __align__(16) __half g_xwh[NN * HID];   // fp16 transformed features
__device__ __align__(128) float g_agg[NN * HID];   // single ping buffer (fp32)
__device__ float g_deg[NN];        // deg, then overwritten with dinv = rsqrt(deg)
__device__ int   g_hist[NN];       // in-degree histogram
__device__ int   g_row[NN + 1];    // CSR row offsets (by dst)
__device__ int   g_cursor[NN];     // counting-sort cursors
__device__ int   g_bsum[128];      // scan block sums
__device__ __align__(8) int2 g_edge[NE];  // CSR record: (src, norm-as-bits)
__device__ float g_sums[NG];
__device__ float g_cnt[NG];

// -------------------- init --------------------
__global__ void k_init(int n) {
    int i = blockIdx.x * blockDim.x + threadIdx.x;
    if (i < n) { g_deg[i] = 1.0f; g_hist[i] = 0; }
    if (i < NG) { g_sums[i] = 0.f; g_cnt[i] = 0.f; }
}

// -------------------- degree + histogram (one pass over edges) --------------------
__global__ void k_deg_hist(const int* __restrict__ dst, const float* __restrict__ w, int E) {
    int e = blockIdx.x * blockDim.x + threadIdx.x;
    if (e < E) {
        int d = dst[e];
        atomicAdd(&g_deg[d], w[e]);
        atomicAdd(&g_hist[d], 1);
    }
}

// -------------------- 2-level exclusive scan of g_hist -> g_row --------------------
__global__ __launch_bounds__(1024) void k_scanA(int n) {
    __shared__ int ws[32];
    int t = threadIdx.x;
    int i = blockIdx.x * 1024 + t;
    int v = (i < n) ? g_hist[i] : 0;
    const unsigned full = 0xffffffffu;
    int lane = t & 31, warp = t >> 5;
    int x = v;
    #pragma unroll
    for (int off = 1; off < 32; off <<= 1) {
        int y = __shfl_up_sync(full, x, off);
        if (lane >= off) x += y;
    }
    if (lane == 31) ws[warp] = x;
    __syncthreads();
    if (warp == 0) {
        int y = ws[lane];
        #pragma unroll
        for (int off = 1; off < 32; off <<= 1) {
            int z = __shfl_up_sync(full, y, off);
            if (lane >= off) y += z;
        }
        ws[lane] = y;
    }
    __syncthreads();
    int blockpref = (warp > 0) ? ws[warp - 1] : 0;
    int incl = x + blockpref;
    if (i < n) g_row[i] = incl - v;
    if (t == 1023) g_bsum[blockIdx.x] = incl;
}

__global__ void k_scanB(int nb) {
    if (threadIdx.x == 0) {
        int acc = 0;
        for (int b = 0; b < nb; b++) { int v = g_bsum[b]; g_bsum[b] = acc; acc += v; }
    }
}

// also finalizes dinv = rsqrt(deg) here (merged k_dinv)
__global__ __launch_bounds__(1024) void k_scanC(int n, int E) {
    int i = blockIdx.x * 1024 + threadIdx.x;
    if (i < n) {
        int r = g_row[i] + g_bsum[blockIdx.x];
        g_row[i] = r;
        g_cursor[i] = r;
        g_deg[i] = rsqrtf(g_deg[i]);
    }
    if (i == 0) g_row[n] = E;
}

// -------------------- counting-sort fill: packed (src, norm) by dst --------------------
__global__ void k_fill(const int* __restrict__ src, const int* __restrict__ dst,
                       const float* __restrict__ w, int E) {
    int e = blockIdx.x * blockDim.x + threadIdx.x;
    if (e < E) {
        int s = src[e], d = dst[e];
        float nv = g_deg[s] * w[e] * g_deg[d];   // g_deg holds dinv
        int pos = atomicAdd(&g_cursor[d], 1);
        int2 rec; rec.x = s; rec.y = __float_as_int(nv);
        g_edge[pos] = rec;
    }
}

// -------------------- GEMM: xwh = half( act(X) @ W ) --------------------
__global__ __launch_bounds__(256) void k_gemm(
    const float* __restrict__ Xext, const float* __restrict__ W,
    int use_ext, int relu_in, int n)
{
    __shared__ float Ws[64 * 64];
    __shared__ float Xs[64 * 65];

    const float* X = use_ext ? Xext : g_agg;

    int tid = threadIdx.x;
    int row0 = blockIdx.x * 64;

    const float4* W4 = (const float4*)W;
    float4* Ws4 = (float4*)Ws;
    #pragma unroll
    for (int i = 0; i < 4; i++) Ws4[tid + 256 * i] = W4[tid + 256 * i];

    const float4* X4 = (const float4*)(X + (size_t)row0 * 64);
    #pragma unroll
    for (int i = 0; i < 4; i++) {
        int idx = tid + 256 * i;
        int r = idx >> 4, c4 = idx & 15;
        if (row0 + r < n) {
            float4 v = X4[idx];
            if (relu_in) {
                v.x = fmaxf(v.x, 0.f); v.y = fmaxf(v.y, 0.f);
                v.z = fmaxf(v.z, 0.f); v.w = fmaxf(v.w, 0.f);
            }
            float* p = &Xs[r * 65 + c4 * 4];
            p[0] = v.x; p[1] = v.y; p[2] = v.z; p[3] = v.w;
        }
    }
    __syncthreads();

    int r = tid >> 2;
    int cs = (tid & 3) * 16;
    int row = row0 + r;
    if (row >= n) return;

    float acc[16];
    #pragma unroll
    for (int c = 0; c < 16; c++) acc[c] = 0.f;

    #pragma unroll
    for (int k = 0; k < 64; k++) {
        float xv = Xs[r * 65 + k];
        const float4* wr = (const float4*)&Ws[k * 64 + cs];
        #pragma unroll
        for (int c4 = 0; c4 < 4; c4++) {
            float4 wv = wr[c4];
            acc[c4 * 4 + 0] += xv * wv.x;
            acc[c4 * 4 + 1] += xv * wv.y;
            acc[c4 * 4 + 2] += xv * wv.z;
            acc[c4 * 4 + 3] += xv * wv.w;
        }
    }

    __half2 hh[8];
    #pragma unroll
    for (int i = 0; i < 8; i++)
        hh[i] = __floats2half2_rn(acc[2 * i], acc[2 * i + 1]);
    uint4* dstp = (uint4*)(g_xwh + (size_t)row * 64 + cs);
    dstp[0] = ((uint4*)hh)[0];
    dstp[1] = ((uint4*)hh)[1];
}

// ---- shared gather core: 8 threads/node, each accumulates 8 features in fp32 ----
__device__ __forceinline__ void gather_core(int node, int j, const float* __restrict__ bias,
                                            float* a /*[8]*/)
{
    int start = __ldg(g_row + node);
    int end   = __ldg(g_row + node + 1);
    float dv = __ldg(g_deg + node);
    float inv = dv * dv;

    const uint4* xw = (const uint4*)g_xwh;   // 16B = 8 halfs per slot, 8 slots/row

    // bias + self-loop
    {
        uint4 v = __ldg(&xw[(size_t)node * 8 + j]);
        const __half2* h = (const __half2*)&v;
        const float4* b4 = (const float4*)(bias + j * 8);
        float4 b0 = __ldg(b4), b1 = __ldg(b4 + 1);
        float2 f0 = __half22float2(h[0]), f1 = __half22float2(h[1]);
        float2 f2 = __half22float2(h[2]), f3 = __half22float2(h[3]);
        a[0] = f0.x * inv + b0.x; a[1] = f0.y * inv + b0.y;
        a[2] = f1.x * inv + b0.z; a[3] = f1.y * inv + b0.w;
        a[4] = f2.x * inv + b1.x; a[5] = f2.y * inv + b1.y;
        a[6] = f3.x * inv + b1.z; a[7] = f3.y * inv + b1.w;
    }

    int e = start;
    for (; e + 3 < end; e += 4) {
        int2 p0 = __ldg(g_edge + e);
        int2 p1 = __ldg(g_edge + e + 1);
        int2 p2 = __ldg(g_edge + e + 2);
        int2 p3 = __ldg(g_edge + e + 3);
        uint4 v0 = __ldg(&xw[(size_t)p0.x * 8 + j]);
        uint4 v1 = __ldg(&xw[(size_t)p1.x * 8 + j]);
        uint4 v2 = __ldg(&xw[(size_t)p2.x * 8 + j]);
        uint4 v3 = __ldg(&xw[(size_t)p3.x * 8 + j]);
        #pragma unroll
        for (int q = 0; q < 4; q++) {
            uint4 v = (q == 0) ? v0 : (q == 1) ? v1 : (q == 2) ? v2 : v3;
            float nv = __int_as_float((q == 0) ? p0.y : (q == 1) ? p1.y : (q == 2) ? p2.y : p3.y);
            const __half2* h = (const __half2*)&v;
            float2 f0 = __half22float2(h[0]), f1 = __half22float2(h[1]);
            float2 f2 = __half22float2(h[2]), f3 = __half22float2(h[3]);
            a[0] += f0.x * nv; a[1] += f0.y * nv;
            a[2] += f1.x * nv; a[3] += f1.y * nv;
            a[4] += f2.x * nv; a[5] += f2.y * nv;
            a[6] += f3.x * nv; a[7] += f3.y * nv;
        }
    }
    for (; e < end; e++) {
        int2 p = __ldg(g_edge + e);
        float nv = __int_as_float(p.y);
        uint4 v = __ldg(&xw[(size_t)p.x * 8 + j]);
        const __half2* h = (const __half2*)&v;
        float2 f0 = __half22float2(h[0]), f1 = __half22float2(h[1]);
        float2 f2 = __half22float2(h[2]), f3 = __half22float2(h[3]);
        a[0] += f0.x * nv; a[1] += f0.y * nv;
        a[2] += f1.x * nv; a[3] += f1.y * nv;
        a[4] += f2.x * nv; a[5] += f2.y * nv;
        a[6] += f3.x * nv; a[7] += f3.y * nv;
    }
}

// -------------------- gather -> g_agg (layers 0,1) --------------------
__global__ __launch_bounds__(256) void k_gather(const float* __restrict__ bias, int n)
{
    int t = blockIdx.x * blockDim.x + threadIdx.x;
    int node = t >> 3;
    if (node >= n) return;
    int j = t & 7;

    float a[8];
    gather_core(node, j, bias, a);

    float4* out = (float4*)(g_agg + (size_t)node * 64 + j * 8);
    float4 o0; o0.x = a[0]; o0.y = a[1]; o0.z = a[2]; o0.w = a[3];
    float4 o1; o1.x = a[4]; o1.y = a[5]; o1.z = a[6]; o1.w = a[7];
    out[0] = o0; out[1] = o1;
}

// -------------------- fused final gather + MLP readout + pooling --------------------
// 256 threads = 32 nodes x 8 threads
__global__ __launch_bounds__(256) void k_gather_readout(
    const float* __restrict__ bias,
    const float* __restrict__ Wr0, const float* __restrict__ br0,
    const float* __restrict__ Wr1, const float* __restrict__ br1,
    const int* __restrict__ batch, int n)
{
    __shared__ float aggS[32][72];     // pitch 72: 16B-aligned rows, conflict-safe
    __shared__ float W0s[64 * 32];
    __shared__ float W1s[32];
    __shared__ float b0s[32];

    int tid = threadIdx.x;
    for (int i = tid; i < 2048; i += 256) W0s[i] = Wr0[i];
    if (tid < 32) { W1s[tid] = Wr1[tid]; b0s[tid] = br0[tid]; }

    int node_l = tid >> 3;
    int j = tid & 7;
    int node = blockIdx.x * 32 + node_l;
    bool valid = (node < n);

    if (valid) {
        float a[8];
        gather_core(node, j, bias, a);
        float* row = &aggS[node_l][j * 8];
        #pragma unroll
        for (int q = 0; q < 8; q++) row[q] = a[q];
    }
    __syncthreads();

    // readout: thread computes 4 hidden cols of its node
    float s = 0.f, cv = 0.f;
    int g = -1;
    if (valid) {
        int c0 = j * 4;
        float acc0 = b0s[c0], acc1 = b0s[c0 + 1], acc2 = b0s[c0 + 2], acc3 = b0s[c0 + 3];
        const float* row = aggS[node_l];
        #pragma unroll
        for (int k = 0; k < 64; k++) {
            float v = row[k];
            const float4 wv = *(const float4*)&W0s[k * 32 + c0];
            acc0 += v * wv.x; acc1 += v * wv.y; acc2 += v * wv.z; acc3 += v * wv.w;
        }
        const float4 w1 = *(const float4*)&W1s[c0];
        s = fmaxf(acc0, 0.f) * w1.x + fmaxf(acc1, 0.f) * w1.y
          + fmaxf(acc2, 0.f) * w1.z + fmaxf(acc3, 0.f) * w1.w;
        g = __ldg(batch + node);
    }

    // reduce the 8 partial sums of each node (xor within aligned 8-lane group)
    const unsigned full = 0xffffffffu;
    s += __shfl_xor_sync(full, s, 4);
    s += __shfl_xor_sync(full, s, 2);
    s += __shfl_xor_sync(full, s, 1);

    // keep contribution only on lane j==0 of each node; add final bias there
    if (valid && j == 0) { s += __ldg(br1); cv = 1.f; }
    else { s = 0.f; }

    // warp segmented scan over sorted graph ids (4 nodes per warp)
    int lane = tid & 31;
    #pragma unroll
    for (int off = 1; off < 32; off <<= 1) {
        float so = __shfl_up_sync(full, s, off);
        float co = __shfl_up_sync(full, cv, off);
        int go = __shfl_up_sync(full, g, off);
        if (lane >= off && go == g) { s += so; cv += co; }
    }
    int gn = __shfl_down_sync(full, g, 1);
    if ((lane == 31 || gn != g) && g >= 0) {
        atomicAdd(&g_sums[g], s);
        atomicAdd(&g_cnt[g], cv);
    }
}

__global__ void k_finalize(float* __restrict__ out) {
    int g = threadIdx.x;
    out[g] = g_sums[g] / fmaxf(g_cnt[g], 1.0f);
}

// -------------------- launch --------------------
extern "C" void kernel_launch(void* const* d_in, const int* in_sizes, int n_in,
                              void* d_out, int out_size)
{
    const float* x   = (const float*)d_in[0];
    const int*   ei  = (const int*)d_in[1];
    const float* ew  = (const float*)d_in[2];
    const int* batch = (const int*)d_in[3];
    const float* W0  = (const float*)d_in[4];
    const float* b0  = (const float*)d_in[5];
    const float* W1  = (const float*)d_in[6];
    const float* b1  = (const float*)d_in[7];
    const float* W2  = (const float*)d_in[8];
    const float* b2  = (const float*)d_in[9];
    const float* Wr0 = (const float*)d_in[10];
    const float* br0 = (const float*)d_in[11];
    const float* Wr1 = (const float*)d_in[12];
    const float* br1 = (const float*)d_in[13];
    float* out = (float*)d_out;

    int n = in_sizes[0] / HID;       // 100000
    int E = in_sizes[2];             // 1600000
    const int* src = ei;
    const int* dst = ei + E;

    int nb = (n + 1023) / 1024;

    // ---- CSR build ----
    k_init<<<(n + 255) / 256, 256>>>(n);
    k_deg_hist<<<(E + 255) / 256, 256>>>(dst, ew, E);
    k_scanA<<<nb, 1024>>>(n);
    k_scanB<<<1, 32>>>(nb);
    k_scanC<<<nb, 1024>>>(n, E);
    k_fill<<<(E + 255) / 256, 256>>>(src, dst, ew, E);

    int gb = (n + 63) / 64;
    int ga = (n * 8 + 255) / 256;
    int gf = (n + 31) / 32;

    // layer 0: x -> agg
    k_gemm<<<gb, 256>>>(x, W0, 1, 0, n);
    k_gather<<<ga, 256>>>(b0, n);
    // layer 1: relu(agg) -> agg
    k_gemm<<<gb, 256>>>(nullptr, W1, 0, 1, n);
    k_gather<<<ga, 256>>>(b1, n);
    // layer 2: relu(agg) -> fused gather + readout + pooling
    k_gemm<<<gb, 256>>>(nullptr, W2, 0, 1, n);
    k_gather_readout<<<gf, 256>>>(b2, Wr0, br0, Wr1, br1, batch, n);

    k_finalize<<<1, 256>>>(out);
}